// round 1
// baseline (speedup 1.0000x reference)
#include <cuda_runtime.h>
#include <cstdint>

// Problem constants
#define B_   16
#define H_   224
#define W_   224
#define C_   64
#define HO_  112
#define WO_  112
#define NPATCH (HO_ * WO_)          // 12544 per image
#define TOTPATCH (B_ * NPATCH)      // 200704
#define KSEL 1254

// Scratch: patch scores (then masked gate) — __device__ global, no allocs.
__device__ float g_scores[TOTPATCH];

// ---------------------------------------------------------------------------
// Kernel 1: stride-2 2x2x64 -> 1 channel conv. One warp per patch.
// Patch = two contiguous 512B rows of x; weights = 256 floats (L1-hit).
// ---------------------------------------------------------------------------
__global__ void conv_score_kernel(const float* __restrict__ x,
                                  const float* __restrict__ wk)
{
    const unsigned warp = (blockIdx.x * blockDim.x + threadIdx.x) >> 5;
    const int lane = threadIdx.x & 31;
    if (warp >= TOTPATCH) return;

    const int b   = warp / NPATCH;
    const int rem = warp % NPATCH;
    const int ho  = rem / WO_;
    const int wo  = rem % WO_;

    // base of pixel (b, 2*ho, 2*wo, 0)
    const size_t base = (((size_t)b * H_ + 2 * ho) * W_ + 2 * wo) * C_;
    const float4* xr = reinterpret_cast<const float4*>(x + base);
    const float4* wr = reinterpret_cast<const float4*>(wk);

    // row 0: 128 floats = 32 float4 (lane l takes float4 l)
    float4 a0 = xr[lane];
    float4 w0 = __ldg(&wr[lane]);
    // row 1: offset by one image row = W_*C_ floats = W_*16 float4
    float4 a1 = xr[W_ * (C_ / 4) + lane];
    float4 w1 = __ldg(&wr[32 + lane]);

    float s = a0.x * w0.x + a0.y * w0.y + a0.z * w0.z + a0.w * w0.w
            + a1.x * w1.x + a1.y * w1.y + a1.z * w1.z + a1.w * w1.w;

    #pragma unroll
    for (int off = 16; off; off >>= 1)
        s += __shfl_down_sync(0xffffffffu, s, off);

    if (lane == 0) g_scores[warp] = s;
}

// ---------------------------------------------------------------------------
// Kernel 2: per-image radix select of the K-th largest score, then zero
// everything below it in place. One block per image; scores are L2-hot.
// ---------------------------------------------------------------------------
__device__ __forceinline__ unsigned float_orderable(float f)
{
    unsigned u = __float_as_uint(f);
    return u ^ ((u & 0x80000000u) ? 0xFFFFFFFFu : 0x80000000u);
}

__global__ void select_mask_kernel()
{
    __shared__ unsigned hist[256];
    __shared__ unsigned s_prefix, s_kth;

    const int b   = blockIdx.x;
    const int tid = threadIdx.x;
    float* gb = g_scores + (size_t)b * NPATCH;

    if (tid == 0) { s_prefix = 0u; s_kth = KSEL; }
    unsigned mask = 0u;
    __syncthreads();

    #pragma unroll
    for (int shift = 24; shift >= 0; shift -= 8) {
        if (tid < 256) hist[tid] = 0u;
        __syncthreads();
        const unsigned prefix = s_prefix;
        for (int i = tid; i < NPATCH; i += blockDim.x) {
            unsigned u = float_orderable(gb[i]);
            if ((u & mask) == prefix)
                atomicAdd(&hist[(u >> shift) & 255u], 1u);
        }
        __syncthreads();
        if (tid == 0) {
            unsigned kth = s_kth;
            int d = 255;
            for (; d > 0; --d) {
                if (kth <= hist[d]) break;
                kth -= hist[d];
            }
            s_prefix = prefix | ((unsigned)d << shift);
            s_kth = kth;
        }
        mask |= (255u << shift);
        __syncthreads();
    }

    const unsigned thr = s_prefix;   // orderable key of the K-th largest value
    for (int i = tid; i < NPATCH; i += blockDim.x) {
        float f = gb[i];
        if (float_orderable(f) < thr) gb[i] = 0.0f;
    }
}

// ---------------------------------------------------------------------------
// Kernel 3: y = x * gate[patch]. One float4 per thread; gate via __ldg
// (800 KB, each entry reused 256x -> L2/L1 resident).
// ---------------------------------------------------------------------------
__global__ void apply_gate_kernel(const float* __restrict__ x,
                                  float* __restrict__ y)
{
    const unsigned i4 = blockIdx.x * blockDim.x + threadIdx.x;
    const unsigned total4 = (unsigned)B_ * H_ * W_ * (C_ / 4);  // 12,845,056
    if (i4 >= total4) return;

    const unsigned pix = i4 >> 4;        // 16 float4 per pixel (C=64)
    const unsigned w   = pix % W_;
    const unsigned hp  = pix / W_;
    const unsigned h   = hp % H_;
    const unsigned b   = hp / H_;

    const float gv = __ldg(&g_scores[(size_t)b * NPATCH + (h >> 1) * WO_ + (w >> 1)]);

    float4 v = reinterpret_cast<const float4*>(x)[i4];
    v.x *= gv; v.y *= gv; v.z *= gv; v.w *= gv;
    reinterpret_cast<float4*>(y)[i4] = v;
}

// ---------------------------------------------------------------------------
extern "C" void kernel_launch(void* const* d_in, const int* in_sizes, int n_in,
                              void* d_out, int out_size)
{
    const float* x  = (const float*)d_in[0];   // [16,224,224,64] f32
    const float* wk = (const float*)d_in[1];   // [2,2,64,1] f32
    float* y = (float*)d_out;

    // K1: one warp per patch, 8 warps (256 thr) per block
    {
        const int warps = TOTPATCH;
        const int threads = 256;
        const int blocks = (warps * 32 + threads - 1) / threads;  // 25088
        conv_score_kernel<<<blocks, threads>>>(x, wk);
    }
    // K2: one block per image
    select_mask_kernel<<<B_, 512>>>();
    // K3: one float4 per thread
    {
        const unsigned total4 = (unsigned)B_ * H_ * W_ * (C_ / 4);
        const int threads = 256;
        const unsigned blocks = (total4 + threads - 1) / threads; // 50176
        apply_gate_kernel<<<blocks, threads>>>(x, y);
    }
}

// round 3
// speedup vs baseline: 1.4284x; 1.4284x over previous
#include <cuda_runtime.h>
#include <cstdint>

// Problem constants
#define B_   16
#define H_   224
#define W_   224
#define C_   64
#define HO_  112
#define WO_  112
#define NPATCH (HO_ * WO_)          // 12544 per image
#define TOTPATCH (B_ * NPATCH)      // 200704
#define KSEL 1254

// Scratch: patch scores (then masked gate) — __device__ global, no allocs.
__device__ float g_scores[TOTPATCH];

// ---------------------------------------------------------------------------
// Kernel 1: stride-2 2x2x64 -> 1 channel conv. One warp per FOUR horizontally
// adjacent patches (2 KB contiguous per row, MLP=8 per lane).
// WO_=112 is divisible by 4, so a 4-patch group never straddles a row.
// ---------------------------------------------------------------------------
__global__ void conv_score_kernel(const float* __restrict__ x,
                                  const float* __restrict__ wk)
{
    const unsigned warp = (blockIdx.x * blockDim.x + threadIdx.x) >> 5;
    const int lane = threadIdx.x & 31;
    const unsigned p0 = warp * 4;               // first patch of this group
    if (p0 >= TOTPATCH) return;

    const int b   = p0 / NPATCH;
    const int rem = p0 % NPATCH;
    const int ho  = rem / WO_;
    const int wo  = rem % WO_;                  // multiple of 4

    // base of pixel (b, 2*ho, 2*wo, 0)
    const size_t base = (((size_t)b * H_ + 2 * ho) * W_ + 2 * wo) * C_;
    const float4* xr = reinterpret_cast<const float4*>(x + base);
    const float4* wr = reinterpret_cast<const float4*>(wk);
    const int rs = W_ * (C_ / 4);               // row stride in float4

    const float4 w0 = __ldg(&wr[lane]);         // weights for row 0, elem lane
    const float4 w1 = __ldg(&wr[32 + lane]);    // weights for row 1, elem lane

    float s[4];
    #pragma unroll
    for (int j = 0; j < 4; ++j) {
        float4 a0 = xr[32 * j + lane];          // patch j, row 0
        float4 a1 = xr[rs + 32 * j + lane];     // patch j, row 1
        s[j] = a0.x * w0.x + a0.y * w0.y + a0.z * w0.z + a0.w * w0.w
             + a1.x * w1.x + a1.y * w1.y + a1.z * w1.z + a1.w * w1.w;
    }

    #pragma unroll
    for (int j = 0; j < 4; ++j) {
        #pragma unroll
        for (int off = 16; off; off >>= 1)
            s[j] += __shfl_down_sync(0xffffffffu, s[j], off);
    }

    if (lane == 0) {
        // p0 is 4-aligned -> 16B-aligned float4 store of the 4 scores
        float4 out = make_float4(s[0], s[1], s[2], s[3]);
        *reinterpret_cast<float4*>(&g_scores[p0]) = out;
    }
}

// ---------------------------------------------------------------------------
// Kernel 2: per-image radix select of the K-th largest score, then zero
// everything below it in place. One block per image; scores are L2-hot.
// ---------------------------------------------------------------------------
__device__ __forceinline__ unsigned float_orderable(float f)
{
    unsigned u = __float_as_uint(f);
    return u ^ ((u & 0x80000000u) ? 0xFFFFFFFFu : 0x80000000u);
}

__global__ void select_mask_kernel()
{
    __shared__ unsigned hist[256];
    __shared__ unsigned s_prefix, s_kth;

    const int b   = blockIdx.x;
    const int tid = threadIdx.x;
    float* gb = g_scores + (size_t)b * NPATCH;

    if (tid == 0) { s_prefix = 0u; s_kth = KSEL; }
    unsigned mask = 0u;
    __syncthreads();

    #pragma unroll
    for (int shift = 24; shift >= 0; shift -= 8) {
        if (tid < 256) hist[tid] = 0u;
        __syncthreads();
        const unsigned prefix = s_prefix;
        for (int i = tid; i < NPATCH; i += blockDim.x) {
            unsigned u = float_orderable(gb[i]);
            if ((u & mask) == prefix)
                atomicAdd(&hist[(u >> shift) & 255u], 1u);
        }
        __syncthreads();
        if (tid == 0) {
            unsigned kth = s_kth;
            int d = 255;
            for (; d > 0; --d) {
                if (kth <= hist[d]) break;
                kth -= hist[d];
            }
            s_prefix = prefix | ((unsigned)d << shift);
            s_kth = kth;
        }
        mask |= (255u << shift);
        __syncthreads();
    }

    const unsigned thr = s_prefix;   // orderable key of the K-th largest value
    for (int i = tid; i < NPATCH; i += blockDim.x) {
        float f = gb[i];
        if (float_orderable(f) < thr) gb[i] = 0.0f;
    }
}

// ---------------------------------------------------------------------------
// Kernel 3: y = x * gate[patch], 4 float4 per thread (MLP=4).
// ~90% of patches have gate==0 -> store zeros WITHOUT reading x.
// A warp's 32 float4 = 2 adjacent pixels = one gate value (W even, 32-aligned),
// so the branch is warp-uniform.
// ---------------------------------------------------------------------------
__global__ void apply_gate_kernel(const float* __restrict__ x,
                                  float* __restrict__ y)
{
    const unsigned total4 = (unsigned)B_ * H_ * W_ * (C_ / 4);  // 12,845,056
    unsigned i4 = blockIdx.x * (blockDim.x * 4u) + threadIdx.x;

    #pragma unroll
    for (int it = 0; it < 4; ++it, i4 += blockDim.x) {
        if (i4 >= total4) break;

        const unsigned pix = i4 >> 4;        // 16 float4 per pixel (C=64)
        const unsigned w   = pix % W_;
        const unsigned hp  = pix / W_;
        const unsigned h   = hp % H_;
        const unsigned b   = hp / H_;

        const float gv = __ldg(&g_scores[b * NPATCH + (h >> 1) * WO_ + (w >> 1)]);

        float4 v;
        if (gv != 0.0f) {
            v = __ldg(reinterpret_cast<const float4*>(x) + i4);
            v.x *= gv; v.y *= gv; v.z *= gv; v.w *= gv;
        } else {
            v = make_float4(0.f, 0.f, 0.f, 0.f);
        }
        reinterpret_cast<float4*>(y)[i4] = v;
    }
}

// ---------------------------------------------------------------------------
extern "C" void kernel_launch(void* const* d_in, const int* in_sizes, int n_in,
                              void* d_out, int out_size)
{
    const float* x  = (const float*)d_in[0];   // [16,224,224,64] f32
    const float* wk = (const float*)d_in[1];   // [2,2,64,1] f32
    float* y = (float*)d_out;

    // K1: one warp per 4 patches, 8 warps (256 thr) per block
    {
        const int warps = TOTPATCH / 4;                       // 50176
        const int threads = 256;
        const int blocks = (warps * 32 + threads - 1) / threads;  // 6272
        conv_score_kernel<<<blocks, threads>>>(x, wk);
    }
    // K2: one block per image
    select_mask_kernel<<<B_, 512>>>();
    // K3: 4 float4 per thread
    {
        const unsigned total4 = (unsigned)B_ * H_ * W_ * (C_ / 4);
        const int threads = 256;
        const unsigned blocks = (total4 + threads * 4 - 1) / (threads * 4); // 12544
        apply_gate_kernel<<<blocks, threads>>>(x, y);
    }
}

// round 4
// speedup vs baseline: 1.6597x; 1.1619x over previous
#include <cuda_runtime.h>
#include <cstdint>

// Problem constants
#define B_   16
#define H_   224
#define W_   224
#define C_   64
#define HO_  112
#define WO_  112
#define NPATCH (HO_ * WO_)          // 12544 per image
#define TOTPATCH (B_ * NPATCH)      // 200704
#define KSEL 1254

// Scratch: patch scores (then masked gate) — __device__ global, no allocs.
__device__ float g_scores[TOTPATCH];

// ---------------------------------------------------------------------------
// Kernel 1: stride-2 2x2x64 -> 1 channel conv. One warp per EIGHT horizontally
// adjacent patches (4 KB contiguous per row, MLP=16 per lane).
// WO_=112 is divisible by 8, so an 8-patch group never straddles a row.
// ---------------------------------------------------------------------------
__global__ void conv_score_kernel(const float* __restrict__ x,
                                  const float* __restrict__ wk)
{
    const unsigned warp = (blockIdx.x * blockDim.x + threadIdx.x) >> 5;
    const int lane = threadIdx.x & 31;
    const unsigned p0 = warp * 8;               // first patch of this group
    if (p0 >= TOTPATCH) return;

    const int b   = p0 / NPATCH;
    const int rem = p0 % NPATCH;
    const int ho  = rem / WO_;
    const int wo  = rem % WO_;                  // multiple of 8

    // base of pixel (b, 2*ho, 2*wo, 0)
    const size_t base = (((size_t)b * H_ + 2 * ho) * W_ + 2 * wo) * C_;
    const float4* xr = reinterpret_cast<const float4*>(x + base);
    const float4* wr = reinterpret_cast<const float4*>(wk);
    const int rs = W_ * (C_ / 4);               // row stride in float4

    const float4 w0 = __ldg(&wr[lane]);         // weights row 0, elem lane
    const float4 w1 = __ldg(&wr[32 + lane]);    // weights row 1, elem lane

    // issue all 16 loads (streaming: x has ~no reuse worth keeping in L2)
    float4 a0[8], a1[8];
    #pragma unroll
    for (int j = 0; j < 8; ++j) a0[j] = __ldcs(&xr[32 * j + lane]);
    #pragma unroll
    for (int j = 0; j < 8; ++j) a1[j] = __ldcs(&xr[rs + 32 * j + lane]);

    float s[8];
    #pragma unroll
    for (int j = 0; j < 8; ++j) {
        s[j] = a0[j].x * w0.x + a0[j].y * w0.y + a0[j].z * w0.z + a0[j].w * w0.w
             + a1[j].x * w1.x + a1[j].y * w1.y + a1[j].z * w1.z + a1[j].w * w1.w;
    }

    #pragma unroll
    for (int j = 0; j < 8; ++j) {
        #pragma unroll
        for (int off = 16; off; off >>= 1)
            s[j] += __shfl_down_sync(0xffffffffu, s[j], off);
    }

    if (lane == 0) {
        // p0 is 8-aligned -> two 16B-aligned float4 stores
        *reinterpret_cast<float4*>(&g_scores[p0])     = make_float4(s[0], s[1], s[2], s[3]);
        *reinterpret_cast<float4*>(&g_scores[p0 + 4]) = make_float4(s[4], s[5], s[6], s[7]);
    }
}

// ---------------------------------------------------------------------------
// Kernel 2: per-image radix select (3 rounds: 11/11/10 bits) of the K-th
// largest score, then zero everything below it in place.
// One block of 1024 threads per image; scores are L2-hot.
// ---------------------------------------------------------------------------
__device__ __forceinline__ unsigned float_orderable(float f)
{
    unsigned u = __float_as_uint(f);
    return u ^ ((u & 0x80000000u) ? 0xFFFFFFFFu : 0x80000000u);
}

__global__ void select_mask_kernel()
{
    __shared__ unsigned hist[2048];
    __shared__ unsigned chunk[64];
    __shared__ unsigned s_prefix, s_kth;

    const int b   = blockIdx.x;
    const int tid = threadIdx.x;
    float* gb = g_scores + (size_t)b * NPATCH;

    if (tid == 0) { s_prefix = 0u; s_kth = KSEL; }
    unsigned mask = 0u;
    __syncthreads();

    const int shifts[3] = {21, 10, 0};
    const int bitsv [3] = {11, 11, 10};

    #pragma unroll
    for (int r = 0; r < 3; ++r) {
        const int shift = shifts[r];
        const unsigned nbins = 1u << bitsv[r];
        const unsigned bmask = nbins - 1u;

        for (unsigned i = tid; i < nbins; i += blockDim.x) hist[i] = 0u;
        __syncthreads();
        const unsigned prefix = s_prefix;
        for (int i = tid; i < NPATCH; i += blockDim.x) {
            unsigned u = float_orderable(gb[i]);
            if ((u & mask) == prefix)
                atomicAdd(&hist[(u >> shift) & bmask], 1u);
        }
        __syncthreads();

        // two-level parallel scan from the top bin down
        const unsigned nchunk = nbins / 32u;
        if ((unsigned)tid < nchunk) {
            unsigned s = 0;
            #pragma unroll 4
            for (int i = 0; i < 32; ++i) s += hist[tid * 32 + i];
            chunk[tid] = s;
        }
        __syncthreads();
        if (tid == 0) {
            unsigned kth = s_kth;
            int c = (int)nchunk - 1;
            for (; c > 0; --c) {
                if (kth <= chunk[c]) break;
                kth -= chunk[c];
            }
            const int base = c * 32;
            int d = 31;
            for (; d > 0; --d) {
                if (kth <= hist[base + d]) break;
                kth -= hist[base + d];
            }
            s_prefix = prefix | ((unsigned)(base + d) << shift);
            s_kth = kth;
        }
        mask |= (bmask << shift);
        __syncthreads();
    }

    const unsigned thr = s_prefix;   // orderable key of the K-th largest value
    for (int i = tid; i < NPATCH; i += blockDim.x) {
        float f = gb[i];
        if (float_orderable(f) < thr) gb[i] = 0.0f;
    }
}

// ---------------------------------------------------------------------------
// Kernel 3: y = x * gate[patch], 8 float4 per thread (MLP=8), exact grid fit.
// ~90% of patches have gate==0 -> store zeros WITHOUT reading x.
// A warp's 32 contiguous float4 = 2 adjacent pixels = one gate value, so the
// branch is warp-uniform. Streaming stores keep the gate array L2-resident.
// ---------------------------------------------------------------------------
__global__ void apply_gate_kernel(const float* __restrict__ x,
                                  float* __restrict__ y)
{
    unsigned i4 = blockIdx.x * (blockDim.x * 8u) + threadIdx.x;

    float gv[8];
    #pragma unroll
    for (int it = 0; it < 8; ++it) {
        const unsigned j4  = i4 + it * 256u;
        const unsigned pix = j4 >> 4;        // 16 float4 per pixel (C=64)
        const unsigned w   = pix % W_;
        const unsigned hp  = pix / W_;
        const unsigned h   = hp % H_;
        const unsigned b   = hp / H_;
        gv[it] = __ldg(&g_scores[b * NPATCH + (h >> 1) * WO_ + (w >> 1)]);
    }

    #pragma unroll
    for (int it = 0; it < 8; ++it) {
        const unsigned j4 = i4 + it * 256u;
        float4 v;
        if (gv[it] != 0.0f) {
            v = __ldcs(reinterpret_cast<const float4*>(x) + j4);
            v.x *= gv[it]; v.y *= gv[it]; v.z *= gv[it]; v.w *= gv[it];
        } else {
            v = make_float4(0.f, 0.f, 0.f, 0.f);
        }
        __stcs(reinterpret_cast<float4*>(y) + j4, v);
    }
}

// ---------------------------------------------------------------------------
extern "C" void kernel_launch(void* const* d_in, const int* in_sizes, int n_in,
                              void* d_out, int out_size)
{
    const float* x  = (const float*)d_in[0];   // [16,224,224,64] f32
    const float* wk = (const float*)d_in[1];   // [2,2,64,1] f32
    float* y = (float*)d_out;

    // K1: one warp per 8 patches, 8 warps (256 thr) per block
    {
        const int warps = TOTPATCH / 8;                           // 25088
        const int threads = 256;
        const int blocks = (warps * 32 + threads - 1) / threads;  // 3136
        conv_score_kernel<<<blocks, threads>>>(x, wk);
    }
    // K2: one block per image
    select_mask_kernel<<<B_, 1024>>>();
    // K3: 8 float4 per thread, exact fit: 12,845,056 / (256*8) = 6272 blocks
    {
        const unsigned total4 = (unsigned)B_ * H_ * W_ * (C_ / 4);
        const int threads = 256;
        const unsigned blocks = total4 / (threads * 8);           // 6272
        apply_gate_kernel<<<blocks, threads>>>(x, y);
    }
}

// round 5
// speedup vs baseline: 1.6694x; 1.0059x over previous
#include <cuda_runtime.h>
#include <cstdint>

// Problem constants
#define B_   16
#define H_   224
#define W_   224
#define C_   64
#define HO_  112
#define WO_  112
#define NPATCH (HO_ * WO_)          // 12544 per image
#define TOTPATCH (B_ * NPATCH)      // 200704
#define KSEL 1254

// Scratch (__device__ globals, no allocs)
__device__ float    g_scores[TOTPATCH];     // conv outputs
__device__ unsigned g_thr[B_];              // per-image K-th-largest orderable key
__device__ unsigned g_cand[TOTPATCH];       // boundary-bin candidate keys

// ---------------------------------------------------------------------------
// Kernel 1: stride-2 2x2x64 -> 1 channel conv. One warp per EIGHT horizontally
// adjacent patches (4 KB contiguous per row, MLP=16 per lane). At HBM ceiling.
// ---------------------------------------------------------------------------
__global__ void conv_score_kernel(const float* __restrict__ x,
                                  const float* __restrict__ wk)
{
    const unsigned warp = (blockIdx.x * blockDim.x + threadIdx.x) >> 5;
    const int lane = threadIdx.x & 31;
    const unsigned p0 = warp * 8;               // first patch of this group
    if (p0 >= TOTPATCH) return;

    const int b   = p0 / NPATCH;
    const int rem = p0 % NPATCH;
    const int ho  = rem / WO_;
    const int wo  = rem % WO_;                  // multiple of 8

    const size_t base = (((size_t)b * H_ + 2 * ho) * W_ + 2 * wo) * C_;
    const float4* xr = reinterpret_cast<const float4*>(x + base);
    const float4* wr = reinterpret_cast<const float4*>(wk);
    const int rs = W_ * (C_ / 4);               // row stride in float4

    const float4 w0 = __ldg(&wr[lane]);
    const float4 w1 = __ldg(&wr[32 + lane]);

    float4 a0[8], a1[8];
    #pragma unroll
    for (int j = 0; j < 8; ++j) a0[j] = __ldcs(&xr[32 * j + lane]);
    #pragma unroll
    for (int j = 0; j < 8; ++j) a1[j] = __ldcs(&xr[rs + 32 * j + lane]);

    float s[8];
    #pragma unroll
    for (int j = 0; j < 8; ++j) {
        s[j] = a0[j].x * w0.x + a0[j].y * w0.y + a0[j].z * w0.z + a0[j].w * w0.w
             + a1[j].x * w1.x + a1[j].y * w1.y + a1[j].z * w1.z + a1[j].w * w1.w;
    }

    #pragma unroll
    for (int j = 0; j < 8; ++j) {
        #pragma unroll
        for (int off = 16; off; off >>= 1)
            s[j] += __shfl_down_sync(0xffffffffu, s[j], off);
    }

    if (lane == 0) {
        *reinterpret_cast<float4*>(&g_scores[p0])     = make_float4(s[0], s[1], s[2], s[3]);
        *reinterpret_cast<float4*>(&g_scores[p0 + 4]) = make_float4(s[4], s[5], s[6], s[7]);
    }
}

// ---------------------------------------------------------------------------
// Kernel 2: per-image K-th-largest threshold via radix select with candidate
// compaction. Round 1: 2048-bin hist over top-11 bits (full scan). Compact the
// boundary bin to g_cand (full scan). Rounds 2-3 run over the tiny candidate
// list. Writes the orderable-key threshold to g_thr[b]; NO mask pass.
// ---------------------------------------------------------------------------
__device__ __forceinline__ unsigned float_orderable(float f)
{
    unsigned u = __float_as_uint(f);
    return u ^ ((u & 0x80000000u) ? 0xFFFFFFFFu : 0x80000000u);
}

__global__ void select_thr_kernel()
{
    __shared__ unsigned hist[2048];
    __shared__ unsigned chunk[64];
    __shared__ unsigned s_prefix, s_kth, s_cnt;

    const int b   = blockIdx.x;
    const int tid = threadIdx.x;
    const float* gb = g_scores + (size_t)b * NPATCH;
    unsigned* cand = g_cand + (size_t)b * NPATCH;

    if (tid == 0) { s_cnt = 0u; }

    // ---- Round 1: full scan, 2048 bins over bits [21..31] ----
    for (int i = tid; i < 2048; i += blockDim.x) hist[i] = 0u;
    __syncthreads();
    for (int i = tid; i < NPATCH; i += blockDim.x) {
        unsigned u = float_orderable(gb[i]);
        atomicAdd(&hist[u >> 21], 1u);
    }
    __syncthreads();
    // two-level top-down scan
    if (tid < 64) {
        unsigned s = 0;
        #pragma unroll 4
        for (int i = 0; i < 32; ++i) s += hist[tid * 32 + i];
        chunk[tid] = s;
    }
    __syncthreads();
    if (tid == 0) {
        unsigned kth = KSEL;
        int c = 63;
        for (; c > 0; --c) { if (kth <= chunk[c]) break; kth -= chunk[c]; }
        const int base = c * 32;
        int d = 31;
        for (; d > 0; --d) { if (kth <= hist[base + d]) break; kth -= hist[base + d]; }
        s_prefix = (unsigned)(base + d) << 21;
        s_kth = kth;
    }
    __syncthreads();
    const unsigned top = s_prefix >> 21;

    // ---- Compact boundary-bin candidates (full scan) ----
    for (int i = tid; i < NPATCH; i += blockDim.x) {
        unsigned u = float_orderable(gb[i]);
        if ((u >> 21) == top) {
            unsigned idx = atomicAdd(&s_cnt, 1u);
            cand[idx] = u;
        }
    }
    __syncthreads();
    const unsigned cnt = s_cnt;

    // ---- Round 2: bits [10..20], 2048 bins over candidates ----
    for (int i = tid; i < 2048; i += blockDim.x) hist[i] = 0u;
    __syncthreads();
    for (unsigned i = tid; i < cnt; i += blockDim.x)
        atomicAdd(&hist[(cand[i] >> 10) & 2047u], 1u);
    __syncthreads();
    if (tid < 64) {
        unsigned s = 0;
        #pragma unroll 4
        for (int i = 0; i < 32; ++i) s += hist[tid * 32 + i];
        chunk[tid] = s;
    }
    __syncthreads();
    if (tid == 0) {
        unsigned kth = s_kth;
        int c = 63;
        for (; c > 0; --c) { if (kth <= chunk[c]) break; kth -= chunk[c]; }
        const int base = c * 32;
        int d = 31;
        for (; d > 0; --d) { if (kth <= hist[base + d]) break; kth -= hist[base + d]; }
        s_prefix |= (unsigned)(base + d) << 10;
        s_kth = kth;
    }
    __syncthreads();
    const unsigned mid = (s_prefix >> 10) & 2047u;

    // ---- Round 3: bits [0..9], 1024 bins over candidates matching mid ----
    for (int i = tid; i < 1024; i += blockDim.x) hist[i] = 0u;
    __syncthreads();
    for (unsigned i = tid; i < cnt; i += blockDim.x) {
        unsigned u = cand[i];
        if (((u >> 10) & 2047u) == mid)
            atomicAdd(&hist[u & 1023u], 1u);
    }
    __syncthreads();
    if (tid < 32) {
        unsigned s = 0;
        #pragma unroll 4
        for (int i = 0; i < 32; ++i) s += hist[tid * 32 + i];
        chunk[tid] = s;
    }
    __syncthreads();
    if (tid == 0) {
        unsigned kth = s_kth;
        int c = 31;
        for (; c > 0; --c) { if (kth <= chunk[c]) break; kth -= chunk[c]; }
        const int base = c * 32;
        int d = 31;
        for (; d > 0; --d) { if (kth <= hist[base + d]) break; kth -= hist[base + d]; }
        g_thr[b] = s_prefix | (unsigned)(base + d);
    }
}

// ---------------------------------------------------------------------------
// Kernel 3: y = x * gate, 16 float4 per thread, blocks exactly aligned to
// images (196 blocks/image). Gate = score if orderable(score) >= thr else 0;
// ~90% of patches are zero -> store zeros WITHOUT reading x (warp-uniform).
// ---------------------------------------------------------------------------
__global__ void apply_gate_kernel(const float* __restrict__ x,
                                  float* __restrict__ y)
{
    const unsigned img = blockIdx.x / 196u;            // block-uniform image
    const unsigned thr = __ldg(&g_thr[img]);
    const unsigned i4  = blockIdx.x * 4096u + threadIdx.x;

    float gv[16];
    #pragma unroll
    for (int it = 0; it < 16; ++it) {
        const unsigned j4  = i4 + it * 256u;
        const unsigned pix = j4 >> 4;                  // 16 float4 per pixel
        const unsigned w   = pix % W_;
        const unsigned hp  = pix / W_;
        const unsigned h   = hp % H_;
        const float s = __ldg(&g_scores[img * NPATCH + (h >> 1) * WO_ + (w >> 1)]);
        gv[it] = (float_orderable(s) >= thr) ? s : 0.0f;
    }

    #pragma unroll
    for (int it = 0; it < 16; ++it) {
        const unsigned j4 = i4 + it * 256u;
        float4 v;
        if (gv[it] != 0.0f) {
            v = __ldcs(reinterpret_cast<const float4*>(x) + j4);
            v.x *= gv[it]; v.y *= gv[it]; v.z *= gv[it]; v.w *= gv[it];
        } else {
            v = make_float4(0.f, 0.f, 0.f, 0.f);
        }
        __stcs(reinterpret_cast<float4*>(y) + j4, v);
    }
}

// ---------------------------------------------------------------------------
extern "C" void kernel_launch(void* const* d_in, const int* in_sizes, int n_in,
                              void* d_out, int out_size)
{
    const float* x  = (const float*)d_in[0];   // [16,224,224,64] f32
    const float* wk = (const float*)d_in[1];   // [2,2,64,1] f32
    float* y = (float*)d_out;

    // K1: one warp per 8 patches
    {
        const int warps = TOTPATCH / 8;                           // 25088
        const int threads = 256;
        const int blocks = (warps * 32 + threads - 1) / threads;  // 3136
        conv_score_kernel<<<blocks, threads>>>(x, wk);
    }
    // K2: one block per image, threshold only (no mask pass)
    select_thr_kernel<<<B_, 1024>>>();
    // K3: 16 float4 per thread, 196 blocks per image (exact fit)
    {
        const unsigned total4 = (unsigned)B_ * H_ * W_ * (C_ / 4); // 12,845,056
        const int threads = 256;
        const unsigned blocks = total4 / (threads * 16);           // 3136
        apply_gate_kernel<<<blocks, threads>>>(x, y);
    }
}

// round 6
// speedup vs baseline: 1.7412x; 1.0430x over previous
#include <cuda_runtime.h>
#include <cstdint>

// Problem constants
#define B_   16
#define H_   224
#define W_   224
#define C_   64
#define HO_  112
#define WO_  112
#define NPATCH (HO_ * WO_)          // 12544 per image
#define TOTPATCH (B_ * NPATCH)      // 200704
#define KSEL 1254
#define KCAP 1280                   // per-image kept-list capacity (tie slack)

// Scratch (__device__ globals, no allocs)
__device__ float    g_scores[TOTPATCH];   // conv outputs
__device__ unsigned g_thr[B_];            // per-image K-th-largest orderable key
__device__ unsigned g_cand[TOTPATCH];     // boundary-bin candidate keys
__device__ int      g_kidx[B_ * KCAP];    // kept patch index (within image)
__device__ float    g_kval[B_ * KCAP];    // kept gate value
__device__ unsigned g_kcnt[B_];           // kept count per image

// ---------------------------------------------------------------------------
// Kernel 1: stride-2 2x2x64 -> 1 channel conv. One warp per EIGHT horizontally
// adjacent patches (4 KB contiguous per row, MLP=16 per lane). At HBM ceiling.
// Block 0 also resets the per-image kept counters for this graph replay.
// ---------------------------------------------------------------------------
__global__ void conv_score_kernel(const float* __restrict__ x,
                                  const float* __restrict__ wk)
{
    if (blockIdx.x == 0 && threadIdx.x < B_) g_kcnt[threadIdx.x] = 0u;

    const unsigned warp = (blockIdx.x * blockDim.x + threadIdx.x) >> 5;
    const int lane = threadIdx.x & 31;
    const unsigned p0 = warp * 8;               // first patch of this group
    if (p0 >= TOTPATCH) return;

    const int b   = p0 / NPATCH;
    const int rem = p0 % NPATCH;
    const int ho  = rem / WO_;
    const int wo  = rem % WO_;                  // multiple of 8

    const size_t base = (((size_t)b * H_ + 2 * ho) * W_ + 2 * wo) * C_;
    const float4* xr = reinterpret_cast<const float4*>(x + base);
    const float4* wr = reinterpret_cast<const float4*>(wk);
    const int rs = W_ * (C_ / 4);               // row stride in float4

    const float4 w0 = __ldg(&wr[lane]);
    const float4 w1 = __ldg(&wr[32 + lane]);

    float4 a0[8], a1[8];
    #pragma unroll
    for (int j = 0; j < 8; ++j) a0[j] = __ldcs(&xr[32 * j + lane]);
    #pragma unroll
    for (int j = 0; j < 8; ++j) a1[j] = __ldcs(&xr[rs + 32 * j + lane]);

    float s[8];
    #pragma unroll
    for (int j = 0; j < 8; ++j) {
        s[j] = a0[j].x * w0.x + a0[j].y * w0.y + a0[j].z * w0.z + a0[j].w * w0.w
             + a1[j].x * w1.x + a1[j].y * w1.y + a1[j].z * w1.z + a1[j].w * w1.w;
    }

    #pragma unroll
    for (int j = 0; j < 8; ++j) {
        #pragma unroll
        for (int off = 16; off; off >>= 1)
            s[j] += __shfl_down_sync(0xffffffffu, s[j], off);
    }

    if (lane == 0) {
        *reinterpret_cast<float4*>(&g_scores[p0])     = make_float4(s[0], s[1], s[2], s[3]);
        *reinterpret_cast<float4*>(&g_scores[p0 + 4]) = make_float4(s[4], s[5], s[6], s[7]);
    }
}

// ---------------------------------------------------------------------------
// Kernel 2: per-image K-th-largest threshold via radix select with candidate
// compaction, then compact the kept (idx, val) list for the scatter kernel.
// One block of 1024 threads per image; scores are L2-hot.
// ---------------------------------------------------------------------------
__device__ __forceinline__ unsigned float_orderable(float f)
{
    unsigned u = __float_as_uint(f);
    return u ^ ((u & 0x80000000u) ? 0xFFFFFFFFu : 0x80000000u);
}

__global__ void select_thr_kernel()
{
    __shared__ unsigned hist[2048];
    __shared__ unsigned chunk[64];
    __shared__ unsigned s_prefix, s_kth, s_cnt, s_kcnt;

    const int b   = blockIdx.x;
    const int tid = threadIdx.x;
    const int lane = tid & 31;
    const float* gb = g_scores + (size_t)b * NPATCH;
    unsigned* cand = g_cand + (size_t)b * NPATCH;

    if (tid == 0) { s_cnt = 0u; s_kcnt = 0u; }

    // ---- Round 1: full scan, 2048 bins over bits [21..31] ----
    for (int i = tid; i < 2048; i += blockDim.x) hist[i] = 0u;
    __syncthreads();
    for (int i = tid; i < NPATCH; i += blockDim.x) {
        unsigned u = float_orderable(gb[i]);
        atomicAdd(&hist[u >> 21], 1u);
    }
    __syncthreads();
    if (tid < 64) {
        unsigned s = 0;
        #pragma unroll 4
        for (int i = 0; i < 32; ++i) s += hist[tid * 32 + i];
        chunk[tid] = s;
    }
    __syncthreads();
    if (tid == 0) {
        unsigned kth = KSEL;
        int c = 63;
        for (; c > 0; --c) { if (kth <= chunk[c]) break; kth -= chunk[c]; }
        const int base = c * 32;
        int d = 31;
        for (; d > 0; --d) { if (kth <= hist[base + d]) break; kth -= hist[base + d]; }
        s_prefix = (unsigned)(base + d) << 21;
        s_kth = kth;
    }
    __syncthreads();
    const unsigned top = s_prefix >> 21;

    // ---- Compact boundary-bin candidates (full scan) ----
    for (int i = tid; i < NPATCH; i += blockDim.x) {
        unsigned u = float_orderable(gb[i]);
        if ((u >> 21) == top) {
            unsigned idx = atomicAdd(&s_cnt, 1u);
            cand[idx] = u;
        }
    }
    __syncthreads();
    const unsigned cnt = s_cnt;

    // ---- Round 2: bits [10..20], 2048 bins over candidates ----
    for (int i = tid; i < 2048; i += blockDim.x) hist[i] = 0u;
    __syncthreads();
    for (unsigned i = tid; i < cnt; i += blockDim.x)
        atomicAdd(&hist[(cand[i] >> 10) & 2047u], 1u);
    __syncthreads();
    if (tid < 64) {
        unsigned s = 0;
        #pragma unroll 4
        for (int i = 0; i < 32; ++i) s += hist[tid * 32 + i];
        chunk[tid] = s;
    }
    __syncthreads();
    if (tid == 0) {
        unsigned kth = s_kth;
        int c = 63;
        for (; c > 0; --c) { if (kth <= chunk[c]) break; kth -= chunk[c]; }
        const int base = c * 32;
        int d = 31;
        for (; d > 0; --d) { if (kth <= hist[base + d]) break; kth -= hist[base + d]; }
        s_prefix |= (unsigned)(base + d) << 10;
        s_kth = kth;
    }
    __syncthreads();
    const unsigned mid = (s_prefix >> 10) & 2047u;

    // ---- Round 3: bits [0..9], 1024 bins over matching candidates ----
    for (int i = tid; i < 1024; i += blockDim.x) hist[i] = 0u;
    __syncthreads();
    for (unsigned i = tid; i < cnt; i += blockDim.x) {
        unsigned u = cand[i];
        if (((u >> 10) & 2047u) == mid)
            atomicAdd(&hist[u & 1023u], 1u);
    }
    __syncthreads();
    if (tid < 32) {
        unsigned s = 0;
        #pragma unroll 4
        for (int i = 0; i < 32; ++i) s += hist[tid * 32 + i];
        chunk[tid] = s;
    }
    __syncthreads();
    if (tid == 0) {
        unsigned kth = s_kth;
        int c = 31;
        for (; c > 0; --c) { if (kth <= chunk[c]) break; kth -= chunk[c]; }
        const int base = c * 32;
        int d = 31;
        for (; d > 0; --d) { if (kth <= hist[base + d]) break; kth -= hist[base + d]; }
        s_prefix |= (unsigned)(base + d);
        g_thr[b] = s_prefix;
    }
    __syncthreads();
    const unsigned thr = s_prefix;

    // ---- Pass 4: compact kept (idx, val) list, warp-aggregated ----
    for (int i = tid; i < NPATCH; i += blockDim.x) {
        const float f = gb[i];
        const bool kept = (float_orderable(f) >= thr);
        const unsigned m = __ballot_sync(0xffffffffu, kept);
        if (kept) {
            const int leader = __ffs(m) - 1;
            unsigned basep = 0;
            if (lane == leader) basep = atomicAdd(&s_kcnt, (unsigned)__popc(m));
            basep = __shfl_sync(m, basep, leader);
            const unsigned slot = basep + __popc(m & ((1u << lane) - 1u));
            if (slot < KCAP) {
                g_kidx[b * KCAP + slot] = i;
                g_kval[b * KCAP + slot] = f;
            }
        }
    }
    __syncthreads();
    if (tid == 0) g_kcnt[b] = (s_kcnt < KCAP) ? s_kcnt : KCAP;
}

// ---------------------------------------------------------------------------
// Kernel 3a: zero-fill of y, skipping kept patches. One block per image row
// (3584 blocks x 256 thr); gates precomputed into smem (112 flags), so the
// store loop is a pure streaming writer with a warp-uniform skip. ~184 MB.
// ---------------------------------------------------------------------------
__global__ void zerofill_kernel(float* __restrict__ y)
{
    __shared__ int s_keep[WO_];

    const unsigned row = blockIdx.x;         // 0 .. B*H-1
    const unsigned b   = row / H_;
    const unsigned h   = row % H_;
    const int tid = threadIdx.x;
    const int wid = tid >> 5;

    if (tid < WO_) {
        const float s = g_scores[b * NPATCH + (h >> 1) * WO_ + tid];
        s_keep[tid] = (float_orderable(s) >= __ldg(&g_thr[b])) ? 1 : 0;
    }
    __syncthreads();

    // row = 224 px * 16 float4 = 3584 float4 = 14 iterations of 256
    float4* yr = reinterpret_cast<float4*>(y) + (size_t)row * (W_ * C_ / 4);
    const float4 z = make_float4(0.f, 0.f, 0.f, 0.f);
    #pragma unroll
    for (int it = 0; it < 14; ++it) {
        // warp wid covers float4 [it*256 + wid*32, +32) = 2 px = gate it*8+wid
        if (!s_keep[it * 8 + wid])
            __stcs(&yr[it * 256 + tid], z);
    }
}

// ---------------------------------------------------------------------------
// Kernel 3b: scatter kept patches. One warp per kept patch: 2 rows x 512 B,
// lane handles one float4 per row. ~42 MB total traffic.
// ---------------------------------------------------------------------------
__global__ void scatter_kernel(const float* __restrict__ x,
                               float* __restrict__ y)
{
    const unsigned w    = (blockIdx.x * blockDim.x + threadIdx.x) >> 5;
    const int lane      = threadIdx.x & 31;
    const unsigned img  = w / KCAP;
    const unsigned slot = w % KCAP;
    if (img >= B_ || slot >= __ldg(&g_kcnt[img])) return;

    const int   p   = g_kidx[img * KCAP + slot];
    const float val = g_kval[img * KCAP + slot];
    const int ho = p / WO_;
    const int wo = p % WO_;

    const size_t base = (((size_t)img * H_ + 2 * ho) * W_ + 2 * wo) * C_;
    const int rs = W_ * (C_ / 4);
    const float4* xr = reinterpret_cast<const float4*>(x + base);
    float4*       yr = reinterpret_cast<float4*>(y + base);

    float4 v0 = __ldg(&xr[lane]);
    float4 v1 = __ldg(&xr[rs + lane]);
    v0.x *= val; v0.y *= val; v0.z *= val; v0.w *= val;
    v1.x *= val; v1.y *= val; v1.z *= val; v1.w *= val;
    __stcs(&yr[lane],      v0);
    __stcs(&yr[rs + lane], v1);
}

// ---------------------------------------------------------------------------
extern "C" void kernel_launch(void* const* d_in, const int* in_sizes, int n_in,
                              void* d_out, int out_size)
{
    const float* x  = (const float*)d_in[0];   // [16,224,224,64] f32
    const float* wk = (const float*)d_in[1];   // [2,2,64,1] f32
    float* y = (float*)d_out;

    // K1: one warp per 8 patches
    {
        const int warps = TOTPATCH / 8;                           // 25088
        const int threads = 256;
        const int blocks = (warps * 32 + threads - 1) / threads;  // 3136
        conv_score_kernel<<<blocks, threads>>>(x, wk);
    }
    // K2: one block per image — threshold + kept-list compaction
    select_thr_kernel<<<B_, 1024>>>();
    // K3a: zero-fill (skip kept), one block per image row
    zerofill_kernel<<<B_ * H_, 256>>>(y);
    // K3b: one warp per kept patch
    {
        const int warps = B_ * KCAP;                              // 20480
        const int threads = 256;
        const int blocks = warps * 32 / threads;                  // 2560
        scatter_kernel<<<blocks, threads>>>(x, y);
    }
}

// round 10
// speedup vs baseline: 1.7838x; 1.0244x over previous
#include <cuda_runtime.h>
#include <cstdint>

// Problem constants
#define B_   16
#define H_   224
#define W_   224
#define C_   64
#define HO_  112
#define WO_  112
#define NPATCH (HO_ * WO_)          // 12544 per image
#define TOTPATCH (B_ * NPATCH)      // 200704
#define KSEL 1254
#define KCAP 1280                   // per-image kept-list capacity (tie slack)

// Scratch (__device__ globals, no allocs)
__device__ float    g_scores[TOTPATCH];   // conv outputs
__device__ unsigned g_thr[B_];            // per-image K-th-largest orderable key
__device__ unsigned g_cand[TOTPATCH];     // boundary-bin candidate keys
__device__ int      g_cidx[TOTPATCH];     // boundary-bin candidate indices
__device__ int      g_kidx[B_ * KCAP];    // kept patch index (within image)
__device__ float    g_kval[B_ * KCAP];    // kept gate value
__device__ unsigned g_kcnt[B_];           // kept count per image

// ---------------------------------------------------------------------------
// Kernel 1: fused conv + zero-fill. One warp per EIGHT horizontally adjacent
// patches: reads its 8 KB x tile (conv scores) AND streams 8 KB of zeros into
// the same region of y (no dependency — scatter overwrites kept patches
// later). Interleaves the 205 MB read with the 205 MB write so HBM runs both
// directions concurrently.
// ---------------------------------------------------------------------------
__global__ void conv_zero_kernel(const float* __restrict__ x,
                                 const float* __restrict__ wk,
                                 float* __restrict__ y)
{
    if (blockIdx.x == 0 && threadIdx.x < B_) g_kcnt[threadIdx.x] = 0u;

    const unsigned warp = (blockIdx.x * blockDim.x + threadIdx.x) >> 5;
    const int lane = threadIdx.x & 31;
    const unsigned p0 = warp * 8;               // first patch of this group
    if (p0 >= TOTPATCH) return;

    const int b   = p0 / NPATCH;
    const int rem = p0 % NPATCH;
    const int ho  = rem / WO_;
    const int wo  = rem % WO_;                  // multiple of 8

    const size_t base = (((size_t)b * H_ + 2 * ho) * W_ + 2 * wo) * C_;
    const float4* xr = reinterpret_cast<const float4*>(x + base);
    float4*       yr = reinterpret_cast<float4*>(y + base);
    const float4* wr = reinterpret_cast<const float4*>(wk);
    const int rs = W_ * (C_ / 4);               // row stride in float4

    const float4 w0 = __ldg(&wr[lane]);
    const float4 w1 = __ldg(&wr[32 + lane]);

    // Issue all 16 loads first (max MLP), then the 16 zero stores.
    float4 a0[8], a1[8];
    #pragma unroll
    for (int j = 0; j < 8; ++j) a0[j] = __ldcs(&xr[32 * j + lane]);
    #pragma unroll
    for (int j = 0; j < 8; ++j) a1[j] = __ldcs(&xr[rs + 32 * j + lane]);

    const float4 z = make_float4(0.f, 0.f, 0.f, 0.f);
    #pragma unroll
    for (int j = 0; j < 8; ++j) __stcs(&yr[32 * j + lane], z);
    #pragma unroll
    for (int j = 0; j < 8; ++j) __stcs(&yr[rs + 32 * j + lane], z);

    float s[8];
    #pragma unroll
    for (int j = 0; j < 8; ++j) {
        s[j] = a0[j].x * w0.x + a0[j].y * w0.y + a0[j].z * w0.z + a0[j].w * w0.w
             + a1[j].x * w1.x + a1[j].y * w1.y + a1[j].z * w1.z + a1[j].w * w1.w;
    }

    #pragma unroll
    for (int j = 0; j < 8; ++j) {
        #pragma unroll
        for (int off = 16; off; off >>= 1)
            s[j] += __shfl_down_sync(0xffffffffu, s[j], off);
    }

    if (lane == 0) {
        *reinterpret_cast<float4*>(&g_scores[p0])     = make_float4(s[0], s[1], s[2], s[3]);
        *reinterpret_cast<float4*>(&g_scores[p0 + 4]) = make_float4(s[4], s[5], s[6], s[7]);
    }
}

// ---------------------------------------------------------------------------
// Kernel 2: per-image K-th-largest threshold via radix select + kept-list
// compaction. All loops containing warp-collective emit_kept are padded to a
// multiple of blockDim.x with a validity predicate, so every lane of every
// warp reaches every __ballot_sync (fixes the round-8 deadlock).
// ---------------------------------------------------------------------------
__device__ __forceinline__ unsigned float_orderable(float f)
{
    unsigned u = __float_as_uint(f);
    return u ^ ((u & 0x80000000u) ? 0xFFFFFFFFu : 0x80000000u);
}

// All 32 lanes of the warp MUST call this (kept=false for inactive work).
__device__ __forceinline__ void emit_kept(int b, unsigned* s_kcnt,
                                          int lane, bool kept, int idx, float val)
{
    const unsigned m = __ballot_sync(0xffffffffu, kept);
    if (kept) {
        const int leader = __ffs(m) - 1;
        unsigned basep = 0;
        if (lane == leader) basep = atomicAdd(s_kcnt, (unsigned)__popc(m));
        basep = __shfl_sync(m, basep, leader);
        const unsigned slot = basep + __popc(m & ((1u << lane) - 1u));
        if (slot < KCAP) {
            g_kidx[b * KCAP + slot] = idx;
            g_kval[b * KCAP + slot] = val;
        }
    }
}

__global__ void select_thr_kernel()
{
    __shared__ unsigned hist[2048];
    __shared__ unsigned chunk[64];
    __shared__ unsigned s_prefix, s_kth, s_cnt, s_kcnt;

    const int b    = blockIdx.x;
    const int tid  = threadIdx.x;
    const int lane = tid & 31;
    const unsigned bdim = blockDim.x;
    const float* gb = g_scores + (size_t)b * NPATCH;
    unsigned* cand = g_cand + (size_t)b * NPATCH;
    int*      cidx = g_cidx + (size_t)b * NPATCH;

    if (tid == 0) { s_cnt = 0u; s_kcnt = 0u; }

    // ---- Round 1: full scan, 2048 bins over bits [21..31] ----
    for (int i = tid; i < 2048; i += bdim) hist[i] = 0u;
    __syncthreads();
    for (int i = tid; i < NPATCH; i += bdim) {
        unsigned u = float_orderable(gb[i]);
        atomicAdd(&hist[u >> 21], 1u);
    }
    __syncthreads();
    if (tid < 64) {
        unsigned s = 0;
        #pragma unroll 4
        for (int i = 0; i < 32; ++i) s += hist[tid * 32 + i];
        chunk[tid] = s;
    }
    __syncthreads();
    if (tid == 0) {
        unsigned kth = KSEL;
        int c = 63;
        for (; c > 0; --c) { if (kth <= chunk[c]) break; kth -= chunk[c]; }
        const int base = c * 32;
        int d = 31;
        for (; d > 0; --d) { if (kth <= hist[base + d]) break; kth -= hist[base + d]; }
        s_prefix = (unsigned)(base + d) << 21;
        s_kth = kth;
    }
    __syncthreads();
    const unsigned top = s_prefix >> 21;

    // ---- Compaction pass: definite keeps + boundary candidates ----
    // Padded loop: every lane executes every emit_kept call.
    {
        const unsigned nloop = ((NPATCH + bdim - 1) / bdim) * bdim;
        for (unsigned i = tid; i < nloop; i += bdim) {
            const bool valid = (i < NPATCH);
            const float f = valid ? gb[i] : 0.0f;
            const unsigned u = float_orderable(f);
            const unsigned bin = u >> 21;
            emit_kept(b, &s_kcnt, lane, valid && (bin > top), (int)i, f);
            if (valid && bin == top) {
                unsigned idx = atomicAdd(&s_cnt, 1u);
                cand[idx] = u;
                cidx[idx] = (int)i;
            }
        }
    }
    __syncthreads();
    const unsigned cnt = s_cnt;

    // ---- Round 2: bits [10..20], 2048 bins over candidates ----
    for (int i = tid; i < 2048; i += bdim) hist[i] = 0u;
    __syncthreads();
    for (unsigned i = tid; i < cnt; i += bdim)
        atomicAdd(&hist[(cand[i] >> 10) & 2047u], 1u);
    __syncthreads();
    if (tid < 64) {
        unsigned s = 0;
        #pragma unroll 4
        for (int i = 0; i < 32; ++i) s += hist[tid * 32 + i];
        chunk[tid] = s;
    }
    __syncthreads();
    if (tid == 0) {
        unsigned kth = s_kth;
        int c = 63;
        for (; c > 0; --c) { if (kth <= chunk[c]) break; kth -= chunk[c]; }
        const int base = c * 32;
        int d = 31;
        for (; d > 0; --d) { if (kth <= hist[base + d]) break; kth -= hist[base + d]; }
        s_prefix |= (unsigned)(base + d) << 10;
        s_kth = kth;
    }
    __syncthreads();
    const unsigned mid = (s_prefix >> 10) & 2047u;

    // ---- Round 3: bits [0..9], 1024 bins over matching candidates ----
    for (int i = tid; i < 1024; i += bdim) hist[i] = 0u;
    __syncthreads();
    for (unsigned i = tid; i < cnt; i += bdim) {
        unsigned u = cand[i];
        if (((u >> 10) & 2047u) == mid)
            atomicAdd(&hist[u & 1023u], 1u);
    }
    __syncthreads();
    if (tid < 32) {
        unsigned s = 0;
        #pragma unroll 4
        for (int i = 0; i < 32; ++i) s += hist[tid * 32 + i];
        chunk[tid] = s;
    }
    __syncthreads();
    if (tid == 0) {
        unsigned kth = s_kth;
        int c = 31;
        for (; c > 0; --c) { if (kth <= chunk[c]) break; kth -= chunk[c]; }
        const int base = c * 32;
        int d = 31;
        for (; d > 0; --d) { if (kth <= hist[base + d]) break; kth -= hist[base + d]; }
        s_prefix |= (unsigned)(base + d);
        g_thr[b] = s_prefix;
    }
    __syncthreads();
    const unsigned thr = s_prefix;

    // ---- Append boundary candidates >= thr (padded loop, warp-safe) ----
    {
        const unsigned nloop = ((cnt + bdim - 1) / bdim) * bdim;
        for (unsigned i = tid; i < nloop; i += bdim) {
            const bool valid = (i < cnt);
            const unsigned u = valid ? cand[i] : 0u;
            const int     id = valid ? cidx[i] : 0;
            const float   fv = __uint_as_float(
                u ^ ((u & 0x80000000u) ? 0x80000000u : 0xFFFFFFFFu));
            emit_kept(b, &s_kcnt, lane, valid && (u >= thr), id, fv);
        }
    }
    __syncthreads();
    if (tid == 0) g_kcnt[b] = (s_kcnt < KCAP) ? s_kcnt : KCAP;
}

// ---------------------------------------------------------------------------
// Kernel 3: scatter kept patches (overwrites the zeros). One warp per FOUR
// kept-list slots: 8 independent float4 loads per lane (MLP=8), then scale
// and store. ~42 MB total traffic.
// ---------------------------------------------------------------------------
__global__ void scatter_kernel(const float* __restrict__ x,
                               float* __restrict__ y)
{
    const unsigned w    = (blockIdx.x * blockDim.x + threadIdx.x) >> 5;
    const int lane      = threadIdx.x & 31;
    const unsigned GRP  = KCAP / 4;            // 320 groups per image
    const unsigned img  = w / GRP;
    const unsigned s0   = (w % GRP) * 4;
    if (img >= B_) return;
    const unsigned kc = __ldg(&g_kcnt[img]);
    const int rs = W_ * (C_ / 4);

    bool act[4];
    float sv[4];
    const float4* xr[4];
    float4* yw[4];
    #pragma unroll
    for (int j = 0; j < 4; ++j) {
        const unsigned slot = s0 + j;
        act[j] = slot < kc;
        const unsigned sl = act[j] ? slot : 0u;
        const int p = g_kidx[img * KCAP + sl];
        sv[j] = g_kval[img * KCAP + sl];
        const int ho = p / WO_;
        const int wo = p % WO_;
        const size_t base = (((size_t)img * H_ + 2 * ho) * W_ + 2 * wo) * C_;
        xr[j] = reinterpret_cast<const float4*>(x + base);
        yw[j] = reinterpret_cast<float4*>(y + base);
    }

    float4 a0[4], a1[4];
    #pragma unroll
    for (int j = 0; j < 4; ++j) {
        if (act[j]) {
            a0[j] = __ldg(&xr[j][lane]);
            a1[j] = __ldg(&xr[j][rs + lane]);
        }
    }
    #pragma unroll
    for (int j = 0; j < 4; ++j) {
        if (act[j]) {
            const float v = sv[j];
            a0[j].x *= v; a0[j].y *= v; a0[j].z *= v; a0[j].w *= v;
            a1[j].x *= v; a1[j].y *= v; a1[j].z *= v; a1[j].w *= v;
            __stcs(&yw[j][lane],      a0[j]);
            __stcs(&yw[j][rs + lane], a1[j]);
        }
    }
}

// ---------------------------------------------------------------------------
extern "C" void kernel_launch(void* const* d_in, const int* in_sizes, int n_in,
                              void* d_out, int out_size)
{
    const float* x  = (const float*)d_in[0];   // [16,224,224,64] f32
    const float* wk = (const float*)d_in[1];   // [2,2,64,1] f32
    float* y = (float*)d_out;

    // K1: fused conv + zero-fill, one warp per 8 patches
    {
        const int warps = TOTPATCH / 8;                           // 25088
        const int threads = 256;
        const int blocks = (warps * 32 + threads - 1) / threads;  // 3136
        conv_zero_kernel<<<blocks, threads>>>(x, wk, y);
    }
    // K2: one block per image — threshold + kept-list compaction
    select_thr_kernel<<<B_, 1024>>>();
    // K3: one warp per 4 kept slots
    {
        const int warps = B_ * (KCAP / 4);                        // 5120
        const int threads = 256;
        const int blocks = warps * 32 / threads;                  // 640
        scatter_kernel<<<blocks, threads>>>(x, y);
    }
}